// round 2
// baseline (speedup 1.0000x reference)
#include <cuda_runtime.h>

// Problem constants (fixed shapes for this benchmark)
#define NN      50000
#define EE      1600000
#define BBATCH  128
#define FIN     20
#define MM      64
#define HH      32
#define JTOT    2048          // M*H
#define KF      44            // restructured per-node feature count
#define JB      256           // j columns per main-kernel block
#define NCHUNKS 37            // 8 * 37 = 296 blocks = 2/SM * 148 SM (one wave)
#define CHUNK   1352          // ceil(50000/37)
#define NIT     64            // nodes per main-loop iteration

#define SMEM_MAIN (KF*JB*4 + KF*NIT*8 + NIT*4)   // W tile + dup'd u tile + batch ids

// ---------------- device scratch (no allocations allowed) ----------------
__device__ __align__(16) float g_rows[NN * 4];
__device__ __align__(16) float g_cols[NN * 4];
__device__ int   g_tag[NN];
__device__ float g_cnt[BBATCH];
__device__ float g_fact[BBATCH];
__device__ float g_sd[BBATCH * FIN];     // raw sum of diag_part per graph
__device__ float g_sa[BBATCH * FIN];     // raw sum of [x, cols] per graph
__device__ __align__(16) float g_u[NN * KF];       // per-node features
__device__ __align__(16) float g_W[KF * JTOT];     // restructured weights
__device__ __align__(16) float g_C[BBATCH * JTOT]; // per-graph constant + bias
__device__ float g_inv[BBATCH * JTOT];             // segment-sum of relu(repr_eq)

// ---------------- packed f32x2 helpers (sm_103a) ----------------
__device__ __forceinline__ unsigned long long ffma2(unsigned long long a,
                                                    unsigned long long b,
                                                    unsigned long long c) {
    unsigned long long d;
    asm("fma.rn.f32x2 %0, %1, %2, %3;" : "=l"(d) : "l"(a), "l"(b), "l"(c));
    return d;
}
__device__ __forceinline__ unsigned long long dup2(float x) {
    unsigned long long r;
    asm("mov.b64 %0, {%1, %2};" : "=l"(r) : "f"(x), "f"(x));
    return r;
}
__device__ __forceinline__ float2 up2(unsigned long long v) {
    float2 r;
    asm("mov.b64 {%0, %1}, %2;" : "=f"(r.x), "=f"(r.y) : "l"(v));
    return r;
}

// ---------------- kernels ----------------
__global__ void k_init() {
    int i = blockIdx.x * 256 + threadIdx.x;
    if (i < NN * 4) { g_rows[i] = 0.f; g_cols[i] = 0.f; }
    if (i < BBATCH * JTOT) g_inv[i] = 0.f;
    if (i < NN) g_tag[i] = -1;
    if (i < BBATCH * FIN) { g_sd[i] = 0.f; g_sa[i] = 0.f; }
    if (i < BBATCH) g_cnt[i] = 0.f;
}

__global__ void k_cnt(const int* __restrict__ batch) {
    __shared__ float s[2];
    __shared__ int sb0;
    int t = threadIdx.x;
    if (t == 0) {
        s[0] = 0.f; s[1] = 0.f;
        sb0 = batch[min(blockIdx.x * 256, NN - 1)];
    }
    __syncthreads();
    int n = blockIdx.x * 256 + t;
    int b0 = sb0;
    if (n < NN) {
        int b = batch[n];
        int d = b - b0;
        if (d >= 0 && d < 2) atomicAdd(&s[d], 1.f);
        else atomicAdd(&g_cnt[b], 1.f);
    }
    __syncthreads();
    if (t < 2 && b0 + t < BBATCH && s[t] != 0.f) atomicAdd(&g_cnt[b0 + t], s[t]);
}

__global__ void k_fact() {
    int t = threadIdx.x;
    if (t < BBATCH) g_fact[t] = 1.f / g_cnt[t];
}

__global__ void k_edges(const int* __restrict__ ei, const float* __restrict__ ea) {
    int e = blockIdx.x * 256 + threadIdx.x;
    if (e >= EE) return;
    int s = ei[e];
    int d = ei[EE + e];
    float4 a = ((const float4*)ea)[e];
    atomicAdd(&g_rows[s * 4 + 0], a.x);
    atomicAdd(&g_rows[s * 4 + 1], a.y);
    atomicAdd(&g_rows[s * 4 + 2], a.z);
    atomicAdd(&g_rows[s * 4 + 3], a.w);
    atomicAdd(&g_cols[d * 4 + 0], a.x);
    atomicAdd(&g_cols[d * 4 + 1], a.y);
    atomicAdd(&g_cols[d * 4 + 2], a.z);
    atomicAdd(&g_cols[d * 4 + 3], a.w);
    if (s == d) atomicMax(&g_tag[s], e);
}

__device__ __forceinline__ float4 fscale(float4 v, float f) {
    return make_float4(v.x * f, v.y * f, v.z * f, v.w * f);
}

__global__ void k_nodeb(const float* __restrict__ x, const float* __restrict__ ea,
                        const int* __restrict__ batch) {
    __shared__ float ssd[2][FIN];
    __shared__ float ssa[2][FIN];
    __shared__ int sb0;
    int t = threadIdx.x;
    if (t == 0) sb0 = batch[min(blockIdx.x * 256, NN - 1)];
    if (t < 2 * FIN) { ((float*)ssd)[t] = 0.f; ((float*)ssa)[t] = 0.f; }
    __syncthreads();
    int n = blockIdx.x * 256 + t;
    int b0 = sb0;
    if (n < NN) {
        int b = batch[n];
        float fact = g_fact[b];
        const float4* xp = (const float4*)(x + (size_t)n * 16);
        float4 x0 = xp[0], x1 = xp[1], x2 = xp[2], x3 = xp[3];
        float4 r = ((const float4*)g_rows)[n];
        float4 c = ((const float4*)g_cols)[n];
        int tag = g_tag[n];
        float4 de = (tag >= 0) ? ((const float4*)ea)[tag] : make_float4(0.f, 0.f, 0.f, 0.f);

        float4* up = (float4*)(g_u + (size_t)n * KF);
        up[0] = x0; up[1] = x1; up[2] = x2; up[3] = x3;       // u[0:16]  = x
        up[4] = de;                                            // u[16:20] = diag_edge
        up[5] = fscale(x0, fact); up[6] = fscale(x1, fact);
        up[7] = fscale(x2, fact); up[8] = fscale(x3, fact);    // u[20:36] = x*fact_n
        up[9] = fscale(r, fact);                               // u[36:40] = rows*fact_n
        up[10] = fscale(c, fact);                              // u[40:44] = cols*fact_n

        int d = b - b0;
        float xf[16] = {x0.x, x0.y, x0.z, x0.w, x1.x, x1.y, x1.z, x1.w,
                        x2.x, x2.y, x2.z, x2.w, x3.x, x3.y, x3.z, x3.w};
        float def[4] = {de.x, de.y, de.z, de.w};
        float cf[4] = {c.x, c.y, c.z, c.w};
        if (d >= 0 && d < 2) {
            #pragma unroll
            for (int f = 0; f < 16; f++) {
                atomicAdd(&ssd[d][f], xf[f]);
                atomicAdd(&ssa[d][f], xf[f]);
            }
            #pragma unroll
            for (int f = 0; f < 4; f++) {
                atomicAdd(&ssd[d][16 + f], def[f]);
                atomicAdd(&ssa[d][16 + f], cf[f]);
            }
        } else {
            #pragma unroll
            for (int f = 0; f < 16; f++) {
                atomicAdd(&g_sd[b * FIN + f], xf[f]);
                atomicAdd(&g_sa[b * FIN + f], xf[f]);
            }
            #pragma unroll
            for (int f = 0; f < 4; f++) {
                atomicAdd(&g_sd[b * FIN + 16 + f], def[f]);
                atomicAdd(&g_sa[b * FIN + 16 + f], cf[f]);
            }
        }
    }
    __syncthreads();
    if (t < 80) {
        int arr = t / 40;
        int rem = t - arr * 40;
        int d = rem / FIN, f = rem - d * FIN;
        int b = b0 + d;
        if (b < BBATCH) {
            float v = arr == 0 ? ssd[d][f] : ssa[d][f];
            if (v != 0.f) atomicAdd(arr == 0 ? &g_sd[b * FIN + f] : &g_sa[b * FIN + f], v);
        }
    }
}

// Build restructured weight matrix W[KF][JTOT] from kernel_equiv (M,5,H,FIN)
__global__ void k_w(const float* __restrict__ ke) {
    int i = blockIdx.x * 256 + threadIdx.x;
    if (i >= KF * JTOT) return;
    int j = i & (JTOT - 1);
    int k = i >> 11;
    int m = j >> 5, h = j & 31;
    const float* base = ke + ((size_t)m * 5) * HH * FIN + h * FIN;  // +b*640 +f
    float w;
    if (k < 20)      w = base[k];                                   // basis 0
    else if (k < 36) w = base[2 * 640 + (k - 20)] + base[3 * 640 + (k - 20)]; // x side of b2+b3
    else if (k < 40) w = base[2 * 640 + (k - 20)];                  // rows side of b2
    else             w = base[3 * 640 + (k - 24)];                  // cols side of b3
    g_W[k * JTOT + j] = w;
}

// Per-graph constant C[b][j] = bias + sum_diag.ke1 + sum_all.ke4
__global__ void k_c(const float* __restrict__ ke, const float* __restrict__ be) {
    __shared__ float sdn[FIN];
    __shared__ float san[FIN];
    int b = blockIdx.x;
    int t = threadIdx.x;
    float fact = g_fact[b];
    if (t < FIN) {
        sdn[t] = g_sd[b * FIN + t] * fact;
        san[t] = g_sa[b * FIN + t] * fact * fact * fact;
    }
    __syncthreads();
    #pragma unroll
    for (int r = 0; r < 8; r++) {
        int j = r * 256 + t;
        int m = j >> 5, h = j & 31;
        const float* k1 = ke + (((size_t)m * 5 + 1) * HH + h) * FIN;
        const float* k4 = ke + (((size_t)m * 5 + 4) * HH + h) * FIN;
        float acc = be[j];
        #pragma unroll
        for (int f = 0; f < FIN; f++) acc += sdn[f] * k1[f] + san[f] * k4[f];
        g_C[b * JTOT + j] = acc;
    }
}

// Main fused kernel: repr_eq = relu(u @ W + C[batch]); segment-sum into g_inv.
extern __shared__ char smem_raw[];
__global__ void __launch_bounds__(256, 2) k_main(const int* __restrict__ batch) {
    float* W_s = (float*)smem_raw;                                        // KF*JB floats
    unsigned long long* u_s = (unsigned long long*)(smem_raw + KF * JB * 4); // KF*NIT dup'd
    int* b_s = (int*)(smem_raw + KF * JB * 4 + KF * NIT * 8);             // NIT ints

    int tid = threadIdx.x;
    int jbase = blockIdx.x * JB;
    int n0 = blockIdx.y * CHUNK;
    int n1 = min(n0 + CHUNK, NN);

    for (int i = tid; i < KF * JB; i += 256) {
        int k = i >> 8;
        int jj = i & 255;
        W_s[i] = g_W[k * JTOT + jbase + jj];
    }

    int jt = tid & 31;
    int nr = tid >> 5;
    int jo = jbase + jt * 8;

    float invacc[8];
    #pragma unroll
    for (int c = 0; c < 8; c++) invacc[c] = 0.f;
    int cur_b = -1;

    for (int base = n0; base < n1; base += NIT) {
        __syncthreads();
        // stage features (transposed + duplicated into f32x2 lanes)
        for (int i = tid; i < NIT * 11; i += 256) {
            int nl = i / 11;
            int q = i - nl * 11;
            int n = base + nl;
            float4 v = make_float4(0.f, 0.f, 0.f, 0.f);
            if (n < n1) v = *(const float4*)(g_u + (size_t)n * KF + (q << 2));
            int k = q << 2;
            u_s[(k + 0) * NIT + nl] = dup2(v.x);
            u_s[(k + 1) * NIT + nl] = dup2(v.y);
            u_s[(k + 2) * NIT + nl] = dup2(v.z);
            u_s[(k + 3) * NIT + nl] = dup2(v.w);
        }
        if (tid < NIT) {
            int n = base + tid;
            b_s[tid] = (n < n1) ? batch[n] : 0;
        }
        __syncthreads();

        unsigned long long acc[8][4];
        #pragma unroll
        for (int i = 0; i < 8; i++)
            #pragma unroll
            for (int p = 0; p < 4; p++) acc[i][p] = 0ULL;

        #pragma unroll 4
        for (int k = 0; k < KF; k++) {
            const ulonglong2* wp = (const ulonglong2*)(W_s + (k << 8) + (jt << 3));
            ulonglong2 wa = wp[0];
            ulonglong2 wb = wp[1];
            const ulonglong2* up = (const ulonglong2*)(u_s + (k << 6) + (nr << 3));
            ulonglong2 ua = up[0], ub = up[1], uc = up[2], ud = up[3];
            unsigned long long uv[8] = {ua.x, ua.y, ub.x, ub.y, uc.x, uc.y, ud.x, ud.y};
            #pragma unroll
            for (int i = 0; i < 8; i++) {
                acc[i][0] = ffma2(uv[i], wa.x, acc[i][0]);
                acc[i][1] = ffma2(uv[i], wa.y, acc[i][1]);
                acc[i][2] = ffma2(uv[i], wb.x, acc[i][2]);
                acc[i][3] = ffma2(uv[i], wb.y, acc[i][3]);
            }
        }

        // epilogue: + C[batch], relu, register-accumulate segment sum
        #pragma unroll
        for (int i = 0; i < 8; i++) {
            int nl = (nr << 3) + i;
            int n = base + nl;
            if (n < n1) {
                int b = b_s[nl];
                if (b != cur_b) {
                    if (cur_b >= 0) {
                        float* gp = g_inv + cur_b * JTOT + jo;
                        #pragma unroll
                        for (int c = 0; c < 8; c++) { atomicAdd(gp + c, invacc[c]); invacc[c] = 0.f; }
                    }
                    cur_b = b;
                }
                const float4* Cp = (const float4*)(g_C + (size_t)b * JTOT + jo);
                float4 c0 = Cp[0], c1 = Cp[1];
                float2 v;
                v = up2(acc[i][0]); invacc[0] += fmaxf(v.x + c0.x, 0.f); invacc[1] += fmaxf(v.y + c0.y, 0.f);
                v = up2(acc[i][1]); invacc[2] += fmaxf(v.x + c0.z, 0.f); invacc[3] += fmaxf(v.y + c0.w, 0.f);
                v = up2(acc[i][2]); invacc[4] += fmaxf(v.x + c1.x, 0.f); invacc[5] += fmaxf(v.y + c1.y, 0.f);
                v = up2(acc[i][3]); invacc[6] += fmaxf(v.x + c1.z, 0.f); invacc[7] += fmaxf(v.y + c1.w, 0.f);
            }
        }
    }
    if (cur_b >= 0) {
        float* gp = g_inv + cur_b * JTOT + jo;
        #pragma unroll
        for (int c = 0; c < 8; c++) atomicAdd(gp + c, invacc[c]);
    }
}

// psi - zerograph = sum_h (inv_basis - relu(bias_eq)) * kernel_inv  (bias_inv cancels)
__global__ void k_final(const float* __restrict__ ki, const float* __restrict__ be,
                        float* __restrict__ out) {
    int i = blockIdx.x * 256 + threadIdx.x;
    if (i >= BBATCH * MM) return;
    int b = i / MM;
    int m = i - b * MM;
    float fact = g_fact[b];
    const float* ip = g_inv + (size_t)b * JTOT + m * HH;
    const float* bp = be + m * HH;
    const float* kp = ki + m * HH;
    float s = 0.f;
    #pragma unroll
    for (int h = 0; h < HH; h++)
        s += (ip[h] * fact - fmaxf(bp[h], 0.f)) * kp[h];
    out[i] = s;
}

// ---------------- launch ----------------
extern "C" void kernel_launch(void* const* d_in, const int* in_sizes, int n_in,
                              void* d_out, int out_size) {
    const float* x  = (const float*)d_in[0];
    const float* ea = (const float*)d_in[1];
    const float* ke = (const float*)d_in[2];
    const float* ki = (const float*)d_in[3];
    const float* be = (const float*)d_in[4];
    // d_in[5] = bias_inv — cancels in psi - zerograph
    const int* ei    = (const int*)d_in[6];
    const int* batch = (const int*)d_in[7];
    float* out = (float*)d_out;

    cudaFuncSetAttribute(k_main, cudaFuncAttributeMaxDynamicSharedMemorySize, SMEM_MAIN);

    k_init<<<1024, 256>>>();
    k_cnt<<<(NN + 255) / 256, 256>>>(batch);
    k_fact<<<1, 128>>>();
    k_edges<<<(EE + 255) / 256, 256>>>(ei, ea);
    k_nodeb<<<(NN + 255) / 256, 256>>>(x, ea, batch);
    k_w<<<(KF * JTOT + 255) / 256, 256>>>(ke);
    k_c<<<BBATCH, 256>>>(ke, be);
    k_main<<<dim3(8, NCHUNKS), 256, SMEM_MAIN>>>(batch);
    k_final<<<(BBATCH * MM + 255) / 256, 256>>>(ki, be, out);
}

// round 4
// speedup vs baseline: 1.0953x; 1.0953x over previous
#include <cuda_runtime.h>

// Problem constants (fixed shapes for this benchmark)
#define NN      50000
#define EE      1600000
#define BBATCH  128
#define FIN     20
#define MM      64
#define HH      32
#define JTOT    2048          // M*H
#define KF      44            // restructured per-node feature count
#define JB      256           // j columns per main-kernel block
#define NCHUNKS 37            // 8 * 37 = 296 blocks = 2/SM * 148 SM (one wave)
#define CHUNK   1352          // ceil(50000/37)
#define NIT     64            // nodes per main-loop iteration

#define SMEM_MAIN (KF*JB*4 + KF*NIT*8 + NIT*4)   // W tile + dup'd u tile + batch ids

// ---------------- device scratch (no allocations allowed) ----------------
__device__ __align__(16) float g_rows[NN * 4];
__device__ __align__(16) float g_cols[NN * 4];
__device__ int   g_tag[NN];
__device__ int   g_startn[BBATCH];
__device__ int   g_endn[BBATCH];
__device__ float g_fact[BBATCH];
__device__ float g_sd[BBATCH * FIN];     // raw sum of diag_part per graph
__device__ float g_sa[BBATCH * FIN];     // raw sum of [x, cols] per graph
__device__ __align__(16) float g_u[NN * KF];       // per-node features
__device__ __align__(16) float g_W[KF * JTOT];     // restructured weights
__device__ __align__(16) float g_C[BBATCH * JTOT]; // per-graph constant + bias
__device__ float g_inv[BBATCH * JTOT];             // segment-sum of relu(repr_eq)

// ---------------- packed f32x2 / vector-red helpers (sm_103a) ----------------
__device__ __forceinline__ unsigned long long ffma2(unsigned long long a,
                                                    unsigned long long b,
                                                    unsigned long long c) {
    unsigned long long d;
    asm("fma.rn.f32x2 %0, %1, %2, %3;" : "=l"(d) : "l"(a), "l"(b), "l"(c));
    return d;
}
__device__ __forceinline__ unsigned long long dup2(float x) {
    unsigned long long r;
    asm("mov.b64 %0, {%1, %2};" : "=l"(r) : "f"(x), "f"(x));
    return r;
}
__device__ __forceinline__ float2 up2(unsigned long long v) {
    float2 r;
    asm("mov.b64 {%0, %1}, %2;" : "=f"(r.x), "=f"(r.y) : "l"(v));
    return r;
}
__device__ __forceinline__ void red4(float* p, float4 v) {
    asm volatile("red.global.add.v4.f32 [%0], {%1, %2, %3, %4};"
                 :: "l"(p), "f"(v.x), "f"(v.y), "f"(v.z), "f"(v.w) : "memory");
}

// ---------------- kernels ----------------
// launch 0: zero scratch + build restructured weights (independent work fused)
__global__ void k_wi(const float* __restrict__ ke) {
    int i = blockIdx.x * 256 + threadIdx.x;
    if (i < NN * 4) { g_rows[i] = 0.f; g_cols[i] = 0.f; }
    if (i < BBATCH * JTOT) g_inv[i] = 0.f;
    if (i < NN) g_tag[i] = -1;
    if (i < BBATCH * FIN) { g_sd[i] = 0.f; g_sa[i] = 0.f; }
    if (i < KF * JTOT) {
        int j = i & (JTOT - 1);
        int k = i >> 11;
        int m = j >> 5, h = j & 31;
        const float* base = ke + ((size_t)m * 5) * HH * FIN + h * FIN;  // +b*640 +f
        float w;
        if (k < 20)      w = base[k];                                   // basis 0
        else if (k < 36) w = base[2 * 640 + (k - 20)] + base[3 * 640 + (k - 20)]; // x of b2+b3
        else if (k < 40) w = base[2 * 640 + (k - 20)];                  // rows of b2
        else             w = base[3 * 640 + (k - 24)];                  // cols of b3
        g_W[k * JTOT + j] = w;
    }
}

// launch 1: graph sizes via sorted-batch boundary detection (single block)
__global__ void k_cntfact(const int* __restrict__ batch) {
    int t = threadIdx.x;
    for (int n = t; n < NN; n += 1024) {
        int b = batch[n];
        if (n == 0 || batch[n - 1] != b) g_startn[b] = n;
        if (n == NN - 1 || batch[n + 1] != b) g_endn[b] = n;
    }
    __syncthreads();
    if (t < BBATCH) g_fact[t] = 1.f / (float)(g_endn[t] - g_startn[t] + 1);
}

// launch 2: edge scatter with vector reductions
__global__ void k_edges(const int* __restrict__ ei, const float* __restrict__ ea) {
    int e = blockIdx.x * 256 + threadIdx.x;
    if (e >= EE) return;
    int s = ei[e];
    int d = ei[EE + e];
    float4 a = ((const float4*)ea)[e];
    red4(&g_rows[s * 4], a);
    red4(&g_cols[d * 4], a);
    if (s == d) atomicMax(&g_tag[s], e);
}

__device__ __forceinline__ float4 fscale(float4 v, float f) {
    return make_float4(v.x * f, v.y * f, v.z * f, v.w * f);
}

// launch 3: per-node feature build + per-graph raw sums
__global__ void k_nodeb(const float* __restrict__ x, const float* __restrict__ ea,
                        const int* __restrict__ batch) {
    __shared__ float ssd[2][FIN];
    __shared__ float ssa[2][FIN];
    __shared__ int sb0;
    int t = threadIdx.x;
    if (t == 0) sb0 = batch[min(blockIdx.x * 256, NN - 1)];
    if (t < 2 * FIN) { ((float*)ssd)[t] = 0.f; ((float*)ssa)[t] = 0.f; }
    __syncthreads();
    int n = blockIdx.x * 256 + t;
    int b0 = sb0;
    if (n < NN) {
        int b = batch[n];
        float fact = g_fact[b];
        const float4* xp = (const float4*)(x + (size_t)n * 16);
        float4 x0 = xp[0], x1 = xp[1], x2 = xp[2], x3 = xp[3];
        float4 r = ((const float4*)g_rows)[n];
        float4 c = ((const float4*)g_cols)[n];
        int tag = g_tag[n];
        float4 de = (tag >= 0) ? ((const float4*)ea)[tag] : make_float4(0.f, 0.f, 0.f, 0.f);

        float4* up = (float4*)(g_u + (size_t)n * KF);
        up[0] = x0; up[1] = x1; up[2] = x2; up[3] = x3;       // u[0:16]  = x
        up[4] = de;                                            // u[16:20] = diag_edge
        up[5] = fscale(x0, fact); up[6] = fscale(x1, fact);
        up[7] = fscale(x2, fact); up[8] = fscale(x3, fact);    // u[20:36] = x*fact_n
        up[9] = fscale(r, fact);                               // u[36:40] = rows*fact_n
        up[10] = fscale(c, fact);                              // u[40:44] = cols*fact_n

        int d = b - b0;
        float xf[16] = {x0.x, x0.y, x0.z, x0.w, x1.x, x1.y, x1.z, x1.w,
                        x2.x, x2.y, x2.z, x2.w, x3.x, x3.y, x3.z, x3.w};
        float def[4] = {de.x, de.y, de.z, de.w};
        float cf[4] = {c.x, c.y, c.z, c.w};
        if (d >= 0 && d < 2) {
            #pragma unroll
            for (int f = 0; f < 16; f++) {
                atomicAdd(&ssd[d][f], xf[f]);
                atomicAdd(&ssa[d][f], xf[f]);
            }
            #pragma unroll
            for (int f = 0; f < 4; f++) {
                atomicAdd(&ssd[d][16 + f], def[f]);
                atomicAdd(&ssa[d][16 + f], cf[f]);
            }
        } else {
            #pragma unroll
            for (int f = 0; f < 16; f++) {
                atomicAdd(&g_sd[b * FIN + f], xf[f]);
                atomicAdd(&g_sa[b * FIN + f], xf[f]);
            }
            #pragma unroll
            for (int f = 0; f < 4; f++) {
                atomicAdd(&g_sd[b * FIN + 16 + f], def[f]);
                atomicAdd(&g_sa[b * FIN + 16 + f], cf[f]);
            }
        }
    }
    __syncthreads();
    if (t < 80) {
        int arr = t / 40;
        int rem = t - arr * 40;
        int d = rem / FIN, f = rem - d * FIN;
        int b = b0 + d;
        if (b < BBATCH) {
            float v = arr == 0 ? ssd[d][f] : ssa[d][f];
            if (v != 0.f) atomicAdd(arr == 0 ? &g_sd[b * FIN + f] : &g_sa[b * FIN + f], v);
        }
    }
}

// launch 4: per-graph constant C[b][j] = bias + sum_diag.ke1 + sum_all.ke4
__global__ void k_c(const float* __restrict__ ke, const float* __restrict__ be) {
    __shared__ float sdn[FIN];
    __shared__ float san[FIN];
    int b = blockIdx.x;
    int t = threadIdx.x;
    float fact = g_fact[b];
    if (t < FIN) {
        sdn[t] = g_sd[b * FIN + t] * fact;
        san[t] = g_sa[b * FIN + t] * fact * fact * fact;
    }
    __syncthreads();
    #pragma unroll
    for (int r = 0; r < 8; r++) {
        int j = r * 256 + t;
        int m = j >> 5, h = j & 31;
        const float* k1 = ke + (((size_t)m * 5 + 1) * HH + h) * FIN;
        const float* k4 = ke + (((size_t)m * 5 + 4) * HH + h) * FIN;
        float acc = be[j];
        #pragma unroll
        for (int f = 0; f < FIN; f++) acc += sdn[f] * k1[f] + san[f] * k4[f];
        g_C[b * JTOT + j] = acc;
    }
}

// launch 5 (ncu-captured): repr_eq = relu(u @ W + C[batch]); segment-sum into g_inv.
extern __shared__ char smem_raw[];
__global__ void __launch_bounds__(256, 2) k_main(const int* __restrict__ batch) {
    float* W_s = (float*)smem_raw;                                        // KF*JB floats
    unsigned long long* u_s = (unsigned long long*)(smem_raw + KF * JB * 4); // KF*NIT dup'd
    int* b_s = (int*)(smem_raw + KF * JB * 4 + KF * NIT * 8);             // NIT ints

    int tid = threadIdx.x;
    int jbase = blockIdx.x * JB;
    int n0 = blockIdx.y * CHUNK;
    int n1 = min(n0 + CHUNK, NN);

    for (int i = tid; i < KF * JB; i += 256) {
        int k = i >> 8;
        int jj = i & 255;
        W_s[i] = g_W[k * JTOT + jbase + jj];
    }

    int jt = tid & 31;
    int nr = tid >> 5;
    int jo = jbase + jt * 8;

    float invacc[8];
    float Cc[8];
    #pragma unroll
    for (int c = 0; c < 8; c++) { invacc[c] = 0.f; Cc[c] = 0.f; }
    int cur_b = -1;

    for (int base = n0; base < n1; base += NIT) {
        __syncthreads();
        // stage features (transposed + duplicated into f32x2 lanes)
        for (int i = tid; i < NIT * 11; i += 256) {
            int nl = i / 11;
            int q = i - nl * 11;
            int n = base + nl;
            float4 v = make_float4(0.f, 0.f, 0.f, 0.f);
            if (n < n1) v = *(const float4*)(g_u + (size_t)n * KF + (q << 2));
            int k = q << 2;
            u_s[(k + 0) * NIT + nl] = dup2(v.x);
            u_s[(k + 1) * NIT + nl] = dup2(v.y);
            u_s[(k + 2) * NIT + nl] = dup2(v.z);
            u_s[(k + 3) * NIT + nl] = dup2(v.w);
        }
        if (tid < NIT) {
            int n = base + tid;
            b_s[tid] = (n < n1) ? batch[n] : 0;
        }
        __syncthreads();

        unsigned long long acc[8][4];
        #pragma unroll
        for (int i = 0; i < 8; i++)
            #pragma unroll
            for (int p = 0; p < 4; p++) acc[i][p] = 0ULL;

        #pragma unroll 4
        for (int k = 0; k < KF; k++) {
            const ulonglong2* wp = (const ulonglong2*)(W_s + (k << 8) + (jt << 3));
            ulonglong2 wa = wp[0];
            ulonglong2 wb = wp[1];
            const ulonglong2* up = (const ulonglong2*)(u_s + (k << 6) + (nr << 3));
            ulonglong2 ua = up[0], ub = up[1], uc = up[2], ud = up[3];
            #pragma unroll
            for (int i = 0; i < 8; i++) {
                unsigned long long uvi =
                    (i == 0) ? ua.x : (i == 1) ? ua.y : (i == 2) ? ub.x : (i == 3) ? ub.y :
                    (i == 4) ? uc.x : (i == 5) ? uc.y : (i == 6) ? ud.x : ud.y;
                acc[i][0] = ffma2(uvi, wa.x, acc[i][0]);
                acc[i][1] = ffma2(uvi, wa.y, acc[i][1]);
                acc[i][2] = ffma2(uvi, wb.x, acc[i][2]);
                acc[i][3] = ffma2(uvi, wb.y, acc[i][3]);
            }
        }

        // epilogue: + C[batch] (register-cached per graph), relu, register segment sum
        #pragma unroll
        for (int i = 0; i < 8; i++) {
            int nl = (nr << 3) + i;
            int n = base + nl;
            if (n < n1) {
                int b = b_s[nl];
                if (b != cur_b) {
                    if (cur_b >= 0) {
                        float* gp = g_inv + cur_b * JTOT + jo;
                        #pragma unroll
                        for (int c = 0; c < 8; c++) { atomicAdd(gp + c, invacc[c]); invacc[c] = 0.f; }
                    }
                    cur_b = b;
                    const float4* Cp = (const float4*)(g_C + (size_t)b * JTOT + jo);
                    float4 c0 = Cp[0], c1 = Cp[1];
                    Cc[0] = c0.x; Cc[1] = c0.y; Cc[2] = c0.z; Cc[3] = c0.w;
                    Cc[4] = c1.x; Cc[5] = c1.y; Cc[6] = c1.z; Cc[7] = c1.w;
                }
                float2 v;
                v = up2(acc[i][0]); invacc[0] += fmaxf(v.x + Cc[0], 0.f); invacc[1] += fmaxf(v.y + Cc[1], 0.f);
                v = up2(acc[i][1]); invacc[2] += fmaxf(v.x + Cc[2], 0.f); invacc[3] += fmaxf(v.y + Cc[3], 0.f);
                v = up2(acc[i][2]); invacc[4] += fmaxf(v.x + Cc[4], 0.f); invacc[5] += fmaxf(v.y + Cc[5], 0.f);
                v = up2(acc[i][3]); invacc[6] += fmaxf(v.x + Cc[6], 0.f); invacc[7] += fmaxf(v.y + Cc[7], 0.f);
            }
        }
    }
    if (cur_b >= 0) {
        float* gp = g_inv + cur_b * JTOT + jo;
        #pragma unroll
        for (int c = 0; c < 8; c++) atomicAdd(gp + c, invacc[c]);
    }
}

// launch 6: psi - zerograph (bias_inv cancels)
__global__ void k_final(const float* __restrict__ ki, const float* __restrict__ be,
                        float* __restrict__ out) {
    int i = blockIdx.x * 256 + threadIdx.x;
    if (i >= BBATCH * MM) return;
    int b = i / MM;
    int m = i - b * MM;
    float fact = g_fact[b];
    const float* ip = g_inv + (size_t)b * JTOT + m * HH;
    const float* bp = be + m * HH;
    const float* kp = ki + m * HH;
    float s = 0.f;
    #pragma unroll
    for (int h = 0; h < HH; h++)
        s += (ip[h] * fact - fmaxf(bp[h], 0.f)) * kp[h];
    out[i] = s;
}

// ---------------- launch ----------------
extern "C" void kernel_launch(void* const* d_in, const int* in_sizes, int n_in,
                              void* d_out, int out_size) {
    const float* x  = (const float*)d_in[0];
    const float* ea = (const float*)d_in[1];
    const float* ke = (const float*)d_in[2];
    const float* ki = (const float*)d_in[3];
    const float* be = (const float*)d_in[4];
    // d_in[5] = bias_inv — cancels in psi - zerograph
    const int* ei    = (const int*)d_in[6];
    const int* batch = (const int*)d_in[7];
    float* out = (float*)d_out;

    cudaFuncSetAttribute(k_main, cudaFuncAttributeMaxDynamicSharedMemorySize, SMEM_MAIN);

    k_wi<<<1024, 256>>>(ke);                              // launch 0
    k_cntfact<<<1, 1024>>>(batch);                        // launch 1
    k_edges<<<(EE + 255) / 256, 256>>>(ei, ea);           // launch 2
    k_nodeb<<<(NN + 255) / 256, 256>>>(x, ea, batch);     // launch 3
    k_c<<<BBATCH, 256>>>(ke, be);                         // launch 4
    k_main<<<dim3(8, NCHUNKS), 256, SMEM_MAIN>>>(batch);  // launch 5  <- ncu -s 5 -c 1
    k_final<<<(BBATCH * MM + 255) / 256, 256>>>(ki, be, out); // launch 6
}

// round 16
// speedup vs baseline: 1.8091x; 1.6517x over previous
#include <cuda_runtime.h>

// Problem constants (fixed shapes for this benchmark)
#define NN      50000
#define EE      1600000
#define BBATCH  128
#define FIN     20
#define MM      64
#define HH      32
#define JTOT    2048          // M*H
#define KF      44            // restructured per-node feature count
#define JB      256           // j columns per main-kernel block
#define NCHUNKS 37            // 8 * 37 = 296 blocks = 2/SM * 148 SM (one wave)
#define CHUNK   1352          // ceil(50000/37)
#define NIT     64            // nodes per main-loop iteration
#define NBF     196           // feature-build blocks in k_build (ceil(50000/256))

#define SMEM_MAIN (KF*JB*4 + KF*NIT*4 + NIT*4)   // W tile + plain u tile + batch ids

// ---------------- device scratch (no allocations allowed) ----------------
__device__ __align__(16) float g_rows[NN * 4];
__device__ __align__(16) float g_cols[NN * 4];
__device__ int   g_tag[NN];
__device__ int   g_startn[BBATCH];
__device__ int   g_endn[BBATCH];
__device__ float g_fact[BBATCH];
__device__ __align__(16) float g_u[NN * KF];       // per-node features
__device__ __align__(16) float g_W[KF * JTOT];     // restructured weights
__device__ __align__(16) float g_C[BBATCH * JTOT]; // per-graph constant + bias
__device__ float g_inv[BBATCH * JTOT];             // segment-sum of relu(repr_eq)

// ---------------- packed f32x2 / vector-red helpers (sm_103a) ----------------
__device__ __forceinline__ unsigned long long ffma2(unsigned long long a,
                                                    unsigned long long b,
                                                    unsigned long long c) {
    unsigned long long d;
    asm("fma.rn.f32x2 %0, %1, %2, %3;" : "=l"(d) : "l"(a), "l"(b), "l"(c));
    return d;
}
__device__ __forceinline__ unsigned long long dup2(float x) {
    unsigned long long r;
    asm("mov.b64 %0, {%1, %2};" : "=l"(r) : "f"(x), "f"(x));
    return r;
}
__device__ __forceinline__ float2 up2(unsigned long long v) {
    float2 r;
    asm("mov.b64 {%0, %1}, %2;" : "=f"(r.x), "=f"(r.y) : "l"(v));
    return r;
}
__device__ __forceinline__ void red4(float* p, float4 v) {
    asm volatile("red.global.add.v4.f32 [%0], {%1, %2, %3, %4};"
                 :: "l"(p), "f"(v.x), "f"(v.y), "f"(v.z), "f"(v.w) : "memory");
}

// ---------------- launch 0: init + weights + graph boundaries ----------------
__global__ void k_pre(const float* __restrict__ ke, const int* __restrict__ batch) {
    int i = blockIdx.x * 256 + threadIdx.x;
    if (i < NN * 4) { g_rows[i] = 0.f; g_cols[i] = 0.f; }
    if (i < BBATCH * JTOT) g_inv[i] = 0.f;
    if (i < NN) {
        g_tag[i] = -1;
        int b = batch[i];
        if (i == 0 || batch[i - 1] != b) g_startn[b] = i;
        if (i == NN - 1 || batch[i + 1] != b) g_endn[b] = i;
    }
    if (i < KF * JTOT) {
        int j = i & (JTOT - 1);
        int k = i >> 11;
        int m = j >> 5, h = j & 31;
        const float* base = ke + ((size_t)m * 5) * HH * FIN + h * FIN;  // +b*640 +f
        float w;
        if (k < 20)      w = base[k];                                   // basis 0
        else if (k < 36) w = base[2 * 640 + (k - 20)] + base[3 * 640 + (k - 20)]; // x of b2+b3
        else if (k < 40) w = base[2 * 640 + (k - 20)];                  // rows of b2
        else             w = base[3 * 640 + (k - 24)];                  // cols of b3
        g_W[k * JTOT + j] = w;
    }
}

// ---------------- launch 1: edge scatter (vector red) + fact compute ----------------
__global__ void k_edges(const int* __restrict__ ei, const float* __restrict__ ea) {
    if (blockIdx.x == 0 && threadIdx.x < BBATCH) {
        int t = threadIdx.x;
        g_fact[t] = 1.f / (float)(g_endn[t] - g_startn[t] + 1);
    }
    int e = blockIdx.x * 256 + threadIdx.x;
    if (e >= EE) return;
    int s = ei[e];
    int d = ei[EE + e];
    float4 a = ((const float4*)ea)[e];
    red4(&g_rows[s * 4], a);
    red4(&g_cols[d * 4], a);
    if (s == d) atomicMax(&g_tag[s], e);
}

__device__ __forceinline__ float4 fscale(float4 v, float f) {
    return make_float4(v.x * f, v.y * f, v.z * f, v.w * f);
}

// ---------------- launch 2: feature build (blocks 0..195) || per-graph sums + C (blocks 196..323) ----
__global__ void k_build(const float* __restrict__ x, const float* __restrict__ ea,
                        const int* __restrict__ batch,
                        const float* __restrict__ ke, const float* __restrict__ be) {
    int bk = blockIdx.x;
    int t = threadIdx.x;

    if (bk < NBF) {
        // --- pure streaming feature build, no atomics, no arrays ---
        int n = bk * 256 + t;
        if (n >= NN) return;
        int b = batch[n];
        float fact = g_fact[b];
        const float4* xp = (const float4*)(x + (size_t)n * 16);
        float4 x0 = xp[0], x1 = xp[1], x2 = xp[2], x3 = xp[3];
        float4 r = ((const float4*)g_rows)[n];
        float4 c = ((const float4*)g_cols)[n];
        int tag = g_tag[n];
        float4 de = (tag >= 0) ? ((const float4*)ea)[tag] : make_float4(0.f, 0.f, 0.f, 0.f);

        float4* up = (float4*)(g_u + (size_t)n * KF);
        up[0] = x0; up[1] = x1; up[2] = x2; up[3] = x3;       // u[0:16]  = x
        up[4] = de;                                            // u[16:20] = diag_edge
        up[5] = fscale(x0, fact); up[6] = fscale(x1, fact);
        up[7] = fscale(x2, fact); up[8] = fscale(x3, fact);    // u[20:36] = x*fact_n
        up[9] = fscale(r, fact);                               // u[36:40] = rows*fact_n
        up[10] = fscale(c, fact);                              // u[40:44] = cols*fact_n
        return;
    }

    // --- per-graph sums (register + shuffle reduce) then C[b][:] ---
    __shared__ float wsum[8 * 24];
    __shared__ float sdn[FIN];
    __shared__ float san[FIN];
    __shared__ float sred[24];

    int b = bk - NBF;
    int n0 = g_startn[b];
    int ne = g_endn[b];

    float s[24];
    #pragma unroll
    for (int q = 0; q < 24; q++) s[q] = 0.f;

    for (int n = n0 + t; n <= ne; n += 256) {
        const float4* xp = (const float4*)(x + (size_t)n * 16);
        float4 x0 = xp[0], x1 = xp[1], x2 = xp[2], x3 = xp[3];
        s[0] += x0.x;  s[1] += x0.y;  s[2] += x0.z;  s[3] += x0.w;
        s[4] += x1.x;  s[5] += x1.y;  s[6] += x1.z;  s[7] += x1.w;
        s[8] += x2.x;  s[9] += x2.y;  s[10] += x2.z; s[11] += x2.w;
        s[12] += x3.x; s[13] += x3.y; s[14] += x3.z; s[15] += x3.w;
        int tag = g_tag[n];
        if (tag >= 0) {
            float4 de = ((const float4*)ea)[tag];
            s[16] += de.x; s[17] += de.y; s[18] += de.z; s[19] += de.w;
        }
        float4 c = ((const float4*)g_cols)[n];
        s[20] += c.x; s[21] += c.y; s[22] += c.z; s[23] += c.w;
    }

    int lane = t & 31, w = t >> 5;
    #pragma unroll
    for (int o = 16; o > 0; o >>= 1)
        #pragma unroll
        for (int q = 0; q < 24; q++)
            s[q] += __shfl_down_sync(0xffffffffu, s[q], o);
    if (lane == 0)
        #pragma unroll
        for (int q = 0; q < 24; q++) wsum[w * 24 + q] = s[q];
    __syncthreads();
    if (t < 24) {
        float v = 0.f;
        #pragma unroll
        for (int ww = 0; ww < 8; ww++) v += wsum[ww * 24 + t];
        sred[t] = v;
    }
    __syncthreads();
    if (t < FIN) {
        float fact = g_fact[b];
        sdn[t] = sred[t] * fact;                                  // fact * sum(diag_part)
        san[t] = (t < 16 ? sred[t] : sred[t + 4]) * fact * fact * fact; // fact^3 * sum([x,cols])
    }
    __syncthreads();

    #pragma unroll
    for (int rr = 0; rr < 8; rr++) {
        int j = rr * 256 + t;
        int m = j >> 5, h = j & 31;
        const float* k1 = ke + (((size_t)m * 5 + 1) * HH + h) * FIN;
        const float* k4 = ke + (((size_t)m * 5 + 4) * HH + h) * FIN;
        float acc = be[j];
        #pragma unroll
        for (int f = 0; f < FIN; f++) acc += sdn[f] * k1[f] + san[f] * k4[f];
        g_C[b * JTOT + j] = acc;
    }
}

// ---------------- launch 3 (ncu-captured): main fused GEMM ----------------
extern __shared__ char smem_raw[];
__global__ void __launch_bounds__(256, 2) k_main(const int* __restrict__ batch) {
    float* W_s = (float*)smem_raw;                                 // KF*JB floats
    float* u_s = (float*)(smem_raw + KF * JB * 4);                 // KF*NIT plain floats
    int* b_s = (int*)(smem_raw + KF * JB * 4 + KF * NIT * 4);      // NIT ints

    int tid = threadIdx.x;
    int jbase = blockIdx.x * JB;
    int n0 = blockIdx.y * CHUNK;
    int n1 = min(n0 + CHUNK, NN);

    for (int i = tid; i < KF * JB; i += 256) {
        int k = i >> 8;
        int jj = i & 255;
        W_s[i] = g_W[k * JTOT + jbase + jj];
    }

    int jt = tid & 31;
    int nr = tid >> 5;
    int jo = jbase + jt * 8;

    float invacc[8];
    float Cc[8];
    #pragma unroll
    for (int c = 0; c < 8; c++) { invacc[c] = 0.f; Cc[c] = 0.f; }
    int cur_b = -1;

    for (int base = n0; base < n1; base += NIT) {
        __syncthreads();
        // stage features transposed: u_s[k][nl] (plain float, dup happens in-register)
        for (int i = tid; i < NIT * 11; i += 256) {
            int nl = i / 11;
            int q = i - nl * 11;
            int n = base + nl;
            float4 v = make_float4(0.f, 0.f, 0.f, 0.f);
            if (n < n1) v = *(const float4*)(g_u + (size_t)n * KF + (q << 2));
            int k = q << 2;
            u_s[(k + 0) * NIT + nl] = v.x;
            u_s[(k + 1) * NIT + nl] = v.y;
            u_s[(k + 2) * NIT + nl] = v.z;
            u_s[(k + 3) * NIT + nl] = v.w;
        }
        if (tid < NIT) {
            int n = base + tid;
            b_s[tid] = (n < n1) ? batch[n] : 0;
        }
        __syncthreads();

        unsigned long long acc[8][4];
        #pragma unroll
        for (int i = 0; i < 8; i++)
            #pragma unroll
            for (int p = 0; p < 4; p++) acc[i][p] = 0ULL;

        #pragma unroll 4
        for (int k = 0; k < KF; k++) {
            const ulonglong2* wp = (const ulonglong2*)(W_s + (k << 8) + (jt << 3));
            ulonglong2 wa = wp[0];
            ulonglong2 wb = wp[1];
            const float4* up = (const float4*)(u_s + (k << 6) + (nr << 3));
            float4 ua = up[0], ub = up[1];
            #pragma unroll
            for (int i = 0; i < 8; i++) {
                float uf =
                    (i == 0) ? ua.x : (i == 1) ? ua.y : (i == 2) ? ua.z : (i == 3) ? ua.w :
                    (i == 4) ? ub.x : (i == 5) ? ub.y : (i == 6) ? ub.z : ub.w;
                unsigned long long uvi = dup2(uf);
                acc[i][0] = ffma2(uvi, wa.x, acc[i][0]);
                acc[i][1] = ffma2(uvi, wa.y, acc[i][1]);
                acc[i][2] = ffma2(uvi, wb.x, acc[i][2]);
                acc[i][3] = ffma2(uvi, wb.y, acc[i][3]);
            }
        }

        // epilogue: + C[batch] (register-cached per graph), relu, register segment sum
        #pragma unroll
        for (int i = 0; i < 8; i++) {
            int nl = (nr << 3) + i;
            int n = base + nl;
            if (n < n1) {
                int b = b_s[nl];
                if (b != cur_b) {
                    if (cur_b >= 0) {
                        float* gp = g_inv + cur_b * JTOT + jo;
                        #pragma unroll
                        for (int c = 0; c < 8; c++) { atomicAdd(gp + c, invacc[c]); invacc[c] = 0.f; }
                    }
                    cur_b = b;
                    const float4* Cp = (const float4*)(g_C + (size_t)b * JTOT + jo);
                    float4 c0 = Cp[0], c1 = Cp[1];
                    Cc[0] = c0.x; Cc[1] = c0.y; Cc[2] = c0.z; Cc[3] = c0.w;
                    Cc[4] = c1.x; Cc[5] = c1.y; Cc[6] = c1.z; Cc[7] = c1.w;
                }
                float2 v;
                v = up2(acc[i][0]); invacc[0] += fmaxf(v.x + Cc[0], 0.f); invacc[1] += fmaxf(v.y + Cc[1], 0.f);
                v = up2(acc[i][1]); invacc[2] += fmaxf(v.x + Cc[2], 0.f); invacc[3] += fmaxf(v.y + Cc[3], 0.f);
                v = up2(acc[i][2]); invacc[4] += fmaxf(v.x + Cc[4], 0.f); invacc[5] += fmaxf(v.y + Cc[5], 0.f);
                v = up2(acc[i][3]); invacc[6] += fmaxf(v.x + Cc[6], 0.f); invacc[7] += fmaxf(v.y + Cc[7], 0.f);
            }
        }
    }
    if (cur_b >= 0) {
        float* gp = g_inv + cur_b * JTOT + jo;
        #pragma unroll
        for (int c = 0; c < 8; c++) atomicAdd(gp + c, invacc[c]);
    }
}

// ---------------- launch 4: psi - zerograph (bias_inv cancels) ----------------
__global__ void k_final(const float* __restrict__ ki, const float* __restrict__ be,
                        float* __restrict__ out) {
    int i = blockIdx.x * 256 + threadIdx.x;
    if (i >= BBATCH * MM) return;
    int b = i / MM;
    int m = i - b * MM;
    float fact = g_fact[b];
    const float* ip = g_inv + (size_t)b * JTOT + m * HH;
    const float* bp = be + m * HH;
    const float* kp = ki + m * HH;
    float s = 0.f;
    #pragma unroll
    for (int h = 0; h < HH; h++)
        s += (ip[h] * fact - fmaxf(bp[h], 0.f)) * kp[h];
    out[i] = s;
}

// ---------------- launch ----------------
extern "C" void kernel_launch(void* const* d_in, const int* in_sizes, int n_in,
                              void* d_out, int out_size) {
    const float* x  = (const float*)d_in[0];
    const float* ea = (const float*)d_in[1];
    const float* ke = (const float*)d_in[2];
    const float* ki = (const float*)d_in[3];
    const float* be = (const float*)d_in[4];
    // d_in[5] = bias_inv — cancels in psi - zerograph
    const int* ei    = (const int*)d_in[6];
    const int* batch = (const int*)d_in[7];
    float* out = (float*)d_out;

    cudaFuncSetAttribute(k_main, cudaFuncAttributeMaxDynamicSharedMemorySize, SMEM_MAIN);

    k_pre<<<1024, 256>>>(ke, batch);                          // launch 0
    k_edges<<<(EE + 255) / 256, 256>>>(ei, ea);               // launch 1
    k_build<<<NBF + BBATCH, 256>>>(x, ea, batch, ke, be);     // launch 2
    k_main<<<dim3(8, NCHUNKS), 256, SMEM_MAIN>>>(batch);      // launch 3  <- ncu captures this
    k_final<<<(BBATCH * MM + 255) / 256, 256>>>(ki, be, out); // launch 4
}